// round 12
// baseline (speedup 1.0000x reference)
#include <cuda_runtime.h>
#include <cuda_bf16.h>
#include <cstdint>

// Problem constants
#define Qn 4
#define Kc 2048
#define Dd 256
#define Bb 8
#define Nn 8192
#define NTOK (Bb * Nn)        // 65536 tokens
#define MCHUNK (Nn / Qn)      // 2048 tokens per (b, q) chunk

// Screening GEMM tiling (mma.m16n8k16 bf16 -> f32)
#define TM 128                // tokens per block
#define TILE_N 32             // codes per tile (4 n8-blocks); 2 blocks/SM
#define NTILE (Kc / TILE_N)   // 64 tiles
#define KSTEPS (Dd / 16)      // 16 k-steps

#define LDMAB 264             // padded leading dim (bf16): 528B rows, conflict-free ldsm
#define ROWB  (LDMAB * 2)     // 528 bytes

#define TAU 8e-3f             // certification margin (> 2x worst-case bf16 dot error)

// SMEM layout (bytes). Fixup scratch lives below A (never overwritten by staging).
#define BC_OFF     0                        // int bc[128]          (512 B)
#define CNT_OFF    512                      // int s_nfix, s_ndeep  (8 B)
#define FIXTOK_OFF 520                      // int s_fixtok[128]    (512 B)
#define DEEP_OFF   1032                     // int s_deeptok[128]   (512 B)
#define TOP8_OFF   1544                     // int s_top8c[128*8]   (4096 B)
#define RV_OFF     5640                     // float s_rv[256]      (1024 B)
#define RI_OFF     6664                     // int   s_ri[256]      (1024 B)
#define A_OFF      7936                     // 128-aligned
#define A_BYTES    (TM * ROWB)              // 67584
#define B0_OFF     (A_OFF + A_BYTES)        // 75520
#define B_BYTES    (TILE_N * ROWB)          // 16896
#define B1_OFF     (B0_OFF + B_BYTES)       // 92416
#define SMEM_TOTAL (B1_OFF + B_BYTES)       // 109312  => 2 blocks/SM

// Global scratch (static; no allocs)
__device__ float         g_xn[NTOK * Dd];        // normalized x, fp32 (exact rescore)
__device__ float         g_en[Qn * Kc * Dd];     // normalized embed, fp32 (exact rescore)
__device__ __nv_bfloat16 g_xnb[NTOK * Dd];       // bf16 screen copies
__device__ __nv_bfloat16 g_enb[Qn * Kc * Dd];

// ---------------------------------------------------------------------------
// PTX helpers
// ---------------------------------------------------------------------------
__device__ __forceinline__ void cp16(uint32_t smem_addr, const void* gptr) {
    asm volatile("cp.async.ca.shared.global [%0], [%1], 16;"
                 :: "r"(smem_addr), "l"(gptr));
}
__device__ __forceinline__ void cp_commit() { asm volatile("cp.async.commit_group;"); }
template <int N>
__device__ __forceinline__ void cp_wait() { asm volatile("cp.async.wait_group %0;" :: "n"(N)); }
__device__ __forceinline__ uint32_t smem_u32(const void* p) {
    uint32_t a;
    asm("{ .reg .u64 t; cvta.to.shared.u64 t, %1; cvt.u32.u64 %0, t; }"
        : "=r"(a) : "l"(p));
    return a;
}
__device__ __forceinline__ void ldsm_x4(uint32_t addr, uint32_t& r0, uint32_t& r1,
                                        uint32_t& r2, uint32_t& r3) {
    asm volatile("ldmatrix.sync.aligned.m8n8.x4.shared.b16 {%0,%1,%2,%3}, [%4];"
                 : "=r"(r0), "=r"(r1), "=r"(r2), "=r"(r3) : "r"(addr));
}
__device__ __forceinline__ void mma16816(float* c, const uint32_t* a,
                                         uint32_t b0, uint32_t b1) {
    asm volatile(
        "mma.sync.aligned.m16n8k16.row.col.f32.bf16.bf16.f32 "
        "{%0,%1,%2,%3}, {%4,%5,%6,%7}, {%8,%9}, {%0,%1,%2,%3};"
        : "+f"(c[0]), "+f"(c[1]), "+f"(c[2]), "+f"(c[3])
        : "r"(a[0]), "r"(a[1]), "r"(a[2]), "r"(a[3]), "r"(b0), "r"(b1));
}

// ---------------------------------------------------------------------------
// Kernel 0a/0b: L2 normalize rows, EXACT reference-mimicking fp32 pipeline
// (unfused mul+add, shfl.down tree, sqrt.rn, max 1e-12, div.rn).
// DO NOT CHANGE NUMERICS. Also writes bf16 screen copies.
// ---------------------------------------------------------------------------
__global__ void l2norm_e_kernel(const float* __restrict__ embed) {
    int row  = blockIdx.x * 8 + (threadIdx.x >> 5);
    int lane = threadIdx.x & 31;
    if (row >= Qn * Kc) return;
    const float* r = embed + (size_t)row * Dd;
    float v[8];
    float s = 0.f;
#pragma unroll
    for (int i = 0; i < 8; ++i) {
        v[i] = r[lane + 32 * i];
        s = __fadd_rn(s, __fmul_rn(v[i], v[i]));
    }
#pragma unroll
    for (int o = 16; o; o >>= 1)
        s = __fadd_rn(s, __shfl_down_sync(0xffffffffu, s, o));
    float total = __shfl_sync(0xffffffffu, s, 0);
    float nf = fmaxf(__fsqrt_rn(total), 1e-12f);
#pragma unroll
    for (int i = 0; i < 8; ++i) {
        float nv = __fdiv_rn(v[i], nf);
        size_t idx = (size_t)row * Dd + lane + 32 * i;
        g_en[idx]  = nv;
        g_enb[idx] = __float2bfloat16(nv);
    }
}

__global__ void l2norm_x_kernel(const float* __restrict__ x) {
    int row  = blockIdx.x * 8 + (threadIdx.x >> 5);
    int lane = threadIdx.x & 31;
    if (row >= NTOK) return;
    const float* r = x + (size_t)row * Dd;
    float v[8];
    float s = 0.f;
#pragma unroll
    for (int i = 0; i < 8; ++i) {
        v[i] = r[lane + 32 * i];
        s = __fadd_rn(s, __fmul_rn(v[i], v[i]));
    }
#pragma unroll
    for (int o = 16; o; o >>= 1)
        s = __fadd_rn(s, __shfl_down_sync(0xffffffffu, s, o));
    float total = __shfl_sync(0xffffffffu, s, 0);
    float nf = fmaxf(__fsqrt_rn(total), 1e-12f);
#pragma unroll
    for (int i = 0; i < 8; ++i) {
        float nv = __fdiv_rn(v[i], nf);
        size_t idx = (size_t)row * Dd + lane + 32 * i;
        g_xn[idx]  = nv;
        g_xnb[idx] = __float2bfloat16(nv);
    }
}

// top-8 insertion with (value desc, index asc) ordering
__device__ __forceinline__ void top8_insert(float v, int c, float* tv, int* ti) {
#pragma unroll
    for (int p = 0; p < 8; ++p) {
        bool better = (v > tv[p]) || (v == tv[p] && c < ti[p]);
        if (better) {
            float fv = tv[p]; tv[p] = v; v = fv;
            int   fc = ti[p]; ti[p] = c; c = fc;
        }
    }
}

// ---------------------------------------------------------------------------
// Kernel 1: bf16 mma.sync screening GEMM + IN-BLOCK exact certification.
// 256 threads (8 warps), 2 blocks/SM. Warp w owns tokens [16w,16w+16).
// 64 N-tiles of 32 codes. After the screen: tokens with gap12 < TAU get an
// exact fp32-chain rescore of their top-8 (or a full exact 2048-scan for
// deep ties), all inside this kernel. Exact chain: sequential ascending-d
// __fmaf_rn over g_xn/g_en (bit-exact vs validated rounds 4-6).
// ---------------------------------------------------------------------------
__global__ void __launch_bounds__(256, 2)
pq_mma_kernel(const float* __restrict__ embed,
              float* __restrict__ out,
              long long out_size) {
    extern __shared__ char smem[];
    const uint32_t sb = smem_u32(smem);
    int*   bc        = (int*)(smem + BC_OFF);
    int*   cnt       = (int*)(smem + CNT_OFF);      // [0]=nfix, [1]=ndeep
    int*   s_fixtok  = (int*)(smem + FIXTOK_OFF);
    int*   s_deeptok = (int*)(smem + DEEP_OFF);
    int*   s_top8c   = (int*)(smem + TOP8_OFF);
    float* s_rv      = (float*)(smem + RV_OFF);
    int*   s_ri      = (int*)(smem + RI_OFF);

    const int tid  = threadIdx.x;
    const int wid  = tid >> 5;
    const int lane = tid & 31;
    const int tok0 = blockIdx.x * TM;
    const int q = (tok0 % Nn) / MCHUNK;
    const __nv_bfloat16* Eb = g_enb + (size_t)q * Kc * Dd;

    if (tid == 0) { cnt[0] = 0; cnt[1] = 0; }

    // ---- stage A (128 tokens x 256 bf16, 528B rows) + B tile 0 ----
    for (int i = tid; i < TM * 32; i += 256) {
        int row = i >> 5, seg = i & 31;
        cp16(sb + A_OFF + (uint32_t)row * ROWB + (uint32_t)seg * 16,
             g_xnb + (size_t)(tok0 + row) * Dd + seg * 8);
    }
    for (int i = tid; i < TILE_N * 32; i += 256) {
        int row = i >> 5, seg = i & 31;
        cp16(sb + B0_OFF + (uint32_t)row * ROWB + (uint32_t)seg * 16,
             Eb + (size_t)row * Dd + seg * 8);
    }
    cp_commit();
    cp_wait<0>();
    __syncthreads();

    // A ldsm per-lane base (validated mapping from rounds 9/11)
    const uint32_t a_base = sb + A_OFF
        + (uint32_t)(wid * 16 + ((lane >> 3) & 1) * 8 + (lane & 7)) * ROWB
        + (uint32_t)((lane >> 4) * 8) * 2;

    // B ldsm per-lane offset: groups (bn,k0),(bn,k8),(bn+1,k0),(bn+1,k8)
    const uint32_t b_lane_off =
        (uint32_t)(((lane >> 4) & 1) * 8 + (lane & 7)) * ROWB +
        (uint32_t)(((lane >> 3) & 1) * 8) * 2;

    // per-thread top-8 for two token rows: A = lane>>2, B = lane>>2 + 8
    float tvA[8], tvB[8];
    int   tiA[8], tiB[8];
#pragma unroll
    for (int k = 0; k < 8; ++k) {
        tvA[k] = -3.4e38f; tiA[k] = 0x7fffffff;
        tvB[k] = -3.4e38f; tiB[k] = 0x7fffffff;
    }
    const int cb_lane = (lane & 3) * 2;

    for (int nt = 0; nt < NTILE; ++nt) {
        const uint32_t bbuf = sb + ((nt & 1) ? B1_OFF : B0_OFF);

        // prefetch B(nt+1) into the other buffer (overlaps compute)
        if (nt + 1 < NTILE) {
            uint32_t dstb = sb + (((nt + 1) & 1) ? B1_OFF : B0_OFF);
            for (int i = tid; i < TILE_N * 32; i += 256) {
                int row = i >> 5, seg = i & 31;
                cp16(dstb + (uint32_t)row * ROWB + (uint32_t)seg * 16,
                     Eb + (size_t)((nt + 1) * TILE_N + row) * Dd + seg * 8);
            }
            cp_commit();
        }

        // ---- compute: 16 tokens x 32 codes per warp, K=256 ----
        float c[4][4];
#pragma unroll
        for (int bn = 0; bn < 4; ++bn)
#pragma unroll
            for (int e = 0; e < 4; ++e) c[bn][e] = 0.f;

#pragma unroll
        for (int ks = 0; ks < KSTEPS; ++ks) {
            uint32_t a[4];
            ldsm_x4(a_base + ks * 32, a[0], a[1], a[2], a[3]);
            uint32_t bb[4][2];
#pragma unroll
            for (int p = 0; p < 2; ++p) {
                uint32_t addr = bbuf + (uint32_t)p * (16 * ROWB)
                                + (uint32_t)ks * 32 + b_lane_off;
                ldsm_x4(addr, bb[2 * p][0], bb[2 * p][1],
                        bb[2 * p + 1][0], bb[2 * p + 1][1]);
            }
#pragma unroll
            for (int bn = 0; bn < 4; ++bn)
                mma16816(c[bn], a, bb[bn][0], bb[bn][1]);
        }

        // ---- register fold into top-8 (rows lane>>2 and lane>>2+8) ----
#pragma unroll
        for (int bn = 0; bn < 4; ++bn) {
            const int cbase = nt * TILE_N + bn * 8 + cb_lane;
            if (c[bn][0] > tvA[7]) top8_insert(c[bn][0], cbase,     tvA, tiA);
            if (c[bn][1] > tvA[7]) top8_insert(c[bn][1], cbase + 1, tvA, tiA);
            if (c[bn][2] > tvB[7]) top8_insert(c[bn][2], cbase,     tvB, tiB);
            if (c[bn][3] > tvB[7]) top8_insert(c[bn][3], cbase + 1, tvB, tiB);
        }

        cp_wait<0>();
        __syncthreads();   // B(nt+1) landed; old buf free next iteration
    }

    // ---- merge top-8 across the 4 lanes sharing each token row ----
#pragma unroll
    for (int step = 1; step <= 2; step <<= 1) {
        float ov[8]; int oi[8];
#pragma unroll
        for (int k = 0; k < 8; ++k) {
            ov[k] = __shfl_xor_sync(0xffffffffu, tvA[k], step);
            oi[k] = __shfl_xor_sync(0xffffffffu, tiA[k], step);
        }
#pragma unroll
        for (int k = 0; k < 8; ++k)
            if (ov[k] > tvA[7] || (ov[k] == tvA[7] && oi[k] < tiA[7]))
                top8_insert(ov[k], oi[k], tvA, tiA);
#pragma unroll
        for (int k = 0; k < 8; ++k) {
            ov[k] = __shfl_xor_sync(0xffffffffu, tvB[k], step);
            oi[k] = __shfl_xor_sync(0xffffffffu, tiB[k], step);
        }
#pragma unroll
        for (int k = 0; k < 8; ++k)
            if (ov[k] > tvB[7] || (ov[k] == tvB[7] && oi[k] < tiB[7]))
                top8_insert(ov[k], oi[k], tvB, tiB);
    }

    // ---- in-block classification (lane&3 == 0 owns 2 tokens) ----
    if ((lane & 3) == 0) {
        const int r = lane >> 2;
#pragma unroll
        for (int h = 0; h < 2; ++h) {
            const float* tv = h ? tvB : tvA;
            const int*   ti = h ? tiB : tiA;
            int tlocal = wid * 16 + h * 8 + r;
            bc[tlocal] = ti[0];                      // provisional
            if (tv[0] - tv[1] < TAU) {
                if (tv[0] - tv[7] >= TAU) {
                    int p = atomicAdd(&cnt[0], 1);
                    s_fixtok[p] = tlocal;
#pragma unroll
                    for (int k = 0; k < 8; ++k) s_top8c[tlocal * 8 + k] = ti[k];
                } else {
                    int p = atomicAdd(&cnt[1], 1);
                    s_deeptok[p] = tlocal;
                }
            }
        }
    }
    __syncthreads();

    // ---- fix1-type: exact rescore of 8 candidates (8 lanes per token) ----
    {
        const int nfix = cnt[0];
        for (int base = 0; base < nfix; base += 32) {
            const int eidx = base + (tid >> 3);
            const int slot = tid & 7;
            float v = -3.4e38f;
            int   code = 0x7fffffff;
            if (eidx < nfix) {
                int tl = s_fixtok[eidx];
                code = s_top8c[tl * 8 + slot];
                const float* xr = g_xn + (size_t)(tok0 + tl) * Dd;
                const float* er = g_en + ((size_t)q * Kc + code) * Dd;
                float acc = 0.f;
#pragma unroll 8
                for (int d = 0; d < Dd; ++d) acc = __fmaf_rn(xr[d], er[d], acc);
                v = acc;
            }
#pragma unroll
            for (int o = 4; o; o >>= 1) {
                float ov = __shfl_down_sync(0xffffffffu, v, o);
                int   oi = __shfl_down_sync(0xffffffffu, code, o);
                if (ov > v || (ov == v && oi < code)) { v = ov; code = oi; }
            }
            if (slot == 0 && eidx < nfix) bc[s_fixtok[eidx]] = code;
        }
    }
    __syncthreads();

    // ---- deep ties: full exact 2048-scan, one token at a time ----
    {
        const int ndeep = cnt[1];
        for (int e = 0; e < ndeep; ++e) {
            const int tl = s_deeptok[e];
            const float* xr = g_xn + (size_t)(tok0 + tl) * Dd;
            float best = -3.4e38f;
            int   bi = 0x7fffffff;
            for (int c0 = tid; c0 < Kc; c0 += 256) {
                const float* er = g_en + ((size_t)q * Kc + c0) * Dd;
                float acc = 0.f;
#pragma unroll 8
                for (int d = 0; d < Dd; ++d) acc = __fmaf_rn(xr[d], er[d], acc);
                if (acc > best) { best = acc; bi = c0; }   // ascending: lowest kept
            }
            s_rv[tid] = best;
            s_ri[tid] = bi;
            __syncthreads();
            if (tid == 0) {
                float v = -3.4e38f;
                int   i = 0x7fffffff;
                for (int t = 0; t < 256; ++t)
                    if (s_rv[t] > v || (s_rv[t] == v && s_ri[t] < i)) {
                        v = s_rv[t]; i = s_ri[t];
                    }
                bc[tl] = i;
            }
            __syncthreads();
        }
    }

    // ---- final outputs: encoding + raw-codeword gather (coalesced) ----
    if (tid < TM) {
        long long epos = (long long)NTOK * Dd + (tok0 + tid);
        if (epos < out_size) out[epos] = (float)bc[tid];
    }
    __syncthreads();
    const float* Eqraw = embed + (size_t)q * Kc * Dd;
    for (int i = tid; i < TM * (Dd / 4); i += 256) {
        int token = i >> 6;
        int r = i & 63;
        int code = bc[token];
        ((float4*)(out + (size_t)(tok0 + token) * Dd))[r] =
            ((const float4*)(Eqraw + (size_t)code * Dd))[r];
    }
}

// ---------------------------------------------------------------------------
// Tail: zero-fill vq_loss (and any slack) past quantized+encoding.
// ---------------------------------------------------------------------------
__global__ void zero_tail(float* __restrict__ out, long long start, long long end) {
    long long i = start + (long long)blockIdx.x * blockDim.x + threadIdx.x;
    if (i < end) out[i] = 0.f;
}

extern "C" void kernel_launch(void* const* d_in, const int* in_sizes, int n_in,
                              void* d_out, int out_size) {
    const float* x     = (const float*)d_in[0];
    const float* embed = (const float*)d_in[1];
    if (n_in >= 2 && in_sizes[0] == Qn * Kc * Dd && in_sizes[1] == NTOK * Dd) {
        const float* t = x; x = embed; embed = t;
    }
    float* out = (float*)d_out;

    l2norm_e_kernel<<<(Qn * Kc) / 8, 256>>>(embed);
    l2norm_x_kernel<<<NTOK / 8, 256>>>(x);

    long long tail = (long long)NTOK * Dd + NTOK;
    if ((long long)out_size > tail) {
        long long n = (long long)out_size - tail;
        int blocks = (int)((n + 255) / 256);
        zero_tail<<<blocks, 256>>>(out, tail, (long long)out_size);
    }

    cudaFuncSetAttribute(pq_mma_kernel, cudaFuncAttributeMaxDynamicSharedMemorySize,
                         SMEM_TOTAL);
    pq_mma_kernel<<<NTOK / TM, 256, SMEM_TOTAL>>>(embed, out, (long long)out_size);
}

// round 13
// speedup vs baseline: 1.6051x; 1.6051x over previous
#include <cuda_runtime.h>
#include <cuda_bf16.h>
#include <cstdint>

// Problem constants
#define Qn 4
#define Kc 2048
#define Dd 256
#define Bb 8
#define Nn 8192
#define NTOK (Bb * Nn)        // 65536 tokens
#define MCHUNK (Nn / Qn)      // 2048 tokens per (b, q) chunk

// Screening GEMM tiling (mma.m16n8k16 bf16 -> f32)
#define TM 128                // tokens per block
#define TILE_N 32             // codes per tile (4 n8-blocks); 2 blocks/SM
#define NTILE (Kc / TILE_N)   // 64 tiles
#define KSTEPS (Dd / 16)      // 16 k-steps

#define LDMAB 264             // padded leading dim (bf16): 528B rows, conflict-free ldsm
#define ROWB  (LDMAB * 2)     // 528 bytes

#define TAU 2e-3f             // certification margin (~7 sigma of bf16 screen noise)

#define FROWB 1040            // fixup smem row stride (bytes): 4-way LDS conflict max

// SMEM layout (bytes). Fixup scratch lives below A (never overwritten by staging).
#define BC_OFF     0                        // int bc[128]          (512 B)
#define CNT_OFF    512                      // int s_nfix, s_ndeep  (8 B)
#define FIXTOK_OFF 520                      // int s_fixtok[128]    (512 B)
#define DEEP_OFF   1032                     // int s_deeptok[128]   (512 B)
#define TOP8_OFF   1544                     // int s_top8c[128*8]   (4096 B)
#define RV_OFF     5640                     // float s_rv[256]      (1024 B)
#define RI_OFF     6664                     // int   s_ri[256]      (1024 B)
#define A_OFF      7936                     // 128-aligned
#define A_BYTES    (TM * ROWB)              // 67584
#define B0_OFF     (A_OFF + A_BYTES)        // 75520
#define B_BYTES    (TILE_N * ROWB)          // 16896
#define B1_OFF     (B0_OFF + B_BYTES)       // 92416
#define SMEM_TOTAL (B1_OFF + B_BYTES)       // 109312  => 2 blocks/SM
// fix phase reuse: e-rows at A_OFF (64 x 1040 = 66560 <= 67584),
//                  x-rows at B0_OFF (8 x 1040 = 8320 <= 16896)

// Global scratch (static; no allocs)
__device__ float         g_xn[NTOK * Dd];        // normalized x, fp32 (exact rescore)
__device__ float         g_en[Qn * Kc * Dd];     // normalized embed, fp32 (exact rescore)
__device__ __nv_bfloat16 g_xnb[NTOK * Dd];       // bf16 screen copies
__device__ __nv_bfloat16 g_enb[Qn * Kc * Dd];

// ---------------------------------------------------------------------------
// PTX helpers
// ---------------------------------------------------------------------------
__device__ __forceinline__ void cp16(uint32_t smem_addr, const void* gptr) {
    asm volatile("cp.async.ca.shared.global [%0], [%1], 16;"
                 :: "r"(smem_addr), "l"(gptr));
}
__device__ __forceinline__ void cp_commit() { asm volatile("cp.async.commit_group;"); }
template <int N>
__device__ __forceinline__ void cp_wait() { asm volatile("cp.async.wait_group %0;" :: "n"(N)); }
__device__ __forceinline__ uint32_t smem_u32(const void* p) {
    uint32_t a;
    asm("{ .reg .u64 t; cvta.to.shared.u64 t, %1; cvt.u32.u64 %0, t; }"
        : "=r"(a) : "l"(p));
    return a;
}
__device__ __forceinline__ void ldsm_x4(uint32_t addr, uint32_t& r0, uint32_t& r1,
                                        uint32_t& r2, uint32_t& r3) {
    asm volatile("ldmatrix.sync.aligned.m8n8.x4.shared.b16 {%0,%1,%2,%3}, [%4];"
                 : "=r"(r0), "=r"(r1), "=r"(r2), "=r"(r3) : "r"(addr));
}
__device__ __forceinline__ void mma16816(float* c, const uint32_t* a,
                                         uint32_t b0, uint32_t b1) {
    asm volatile(
        "mma.sync.aligned.m16n8k16.row.col.f32.bf16.bf16.f32 "
        "{%0,%1,%2,%3}, {%4,%5,%6,%7}, {%8,%9}, {%0,%1,%2,%3};"
        : "+f"(c[0]), "+f"(c[1]), "+f"(c[2]), "+f"(c[3])
        : "r"(a[0]), "r"(a[1]), "r"(a[2]), "r"(a[3]), "r"(b0), "r"(b1));
}

// ---------------------------------------------------------------------------
// Kernel 0a/0b: L2 normalize rows, EXACT reference-mimicking fp32 pipeline
// (unfused mul+add, shfl.down tree, sqrt.rn, max 1e-12, div.rn).
// DO NOT CHANGE NUMERICS. Also writes bf16 screen copies.
// ---------------------------------------------------------------------------
__global__ void l2norm_e_kernel(const float* __restrict__ embed) {
    int row  = blockIdx.x * 8 + (threadIdx.x >> 5);
    int lane = threadIdx.x & 31;
    if (row >= Qn * Kc) return;
    const float* r = embed + (size_t)row * Dd;
    float v[8];
    float s = 0.f;
#pragma unroll
    for (int i = 0; i < 8; ++i) {
        v[i] = r[lane + 32 * i];
        s = __fadd_rn(s, __fmul_rn(v[i], v[i]));
    }
#pragma unroll
    for (int o = 16; o; o >>= 1)
        s = __fadd_rn(s, __shfl_down_sync(0xffffffffu, s, o));
    float total = __shfl_sync(0xffffffffu, s, 0);
    float nf = fmaxf(__fsqrt_rn(total), 1e-12f);
#pragma unroll
    for (int i = 0; i < 8; ++i) {
        float nv = __fdiv_rn(v[i], nf);
        size_t idx = (size_t)row * Dd + lane + 32 * i;
        g_en[idx]  = nv;
        g_enb[idx] = __float2bfloat16(nv);
    }
}

__global__ void l2norm_x_kernel(const float* __restrict__ x) {
    int row  = blockIdx.x * 8 + (threadIdx.x >> 5);
    int lane = threadIdx.x & 31;
    if (row >= NTOK) return;
    const float* r = x + (size_t)row * Dd;
    float v[8];
    float s = 0.f;
#pragma unroll
    for (int i = 0; i < 8; ++i) {
        v[i] = r[lane + 32 * i];
        s = __fadd_rn(s, __fmul_rn(v[i], v[i]));
    }
#pragma unroll
    for (int o = 16; o; o >>= 1)
        s = __fadd_rn(s, __shfl_down_sync(0xffffffffu, s, o));
    float total = __shfl_sync(0xffffffffu, s, 0);
    float nf = fmaxf(__fsqrt_rn(total), 1e-12f);
#pragma unroll
    for (int i = 0; i < 8; ++i) {
        float nv = __fdiv_rn(v[i], nf);
        size_t idx = (size_t)row * Dd + lane + 32 * i;
        g_xn[idx]  = nv;
        g_xnb[idx] = __float2bfloat16(nv);
    }
}

// top-8 insertion with (value desc, index asc) ordering
__device__ __forceinline__ void top8_insert(float v, int c, float* tv, int* ti) {
#pragma unroll
    for (int p = 0; p < 8; ++p) {
        bool better = (v > tv[p]) || (v == tv[p] && c < ti[p]);
        if (better) {
            float fv = tv[p]; tv[p] = v; v = fv;
            int   fc = ti[p]; ti[p] = c; c = fc;
        }
    }
}

// ---------------------------------------------------------------------------
// Kernel 1: bf16 mma.sync screening GEMM + IN-BLOCK exact certification.
// 256 threads (8 warps), 2 blocks/SM. Warp w owns tokens [16w,16w+16).
// 64 N-tiles of 32 codes. Uncertain tokens (gap12 < TAU) get an exact
// fp32-chain rescore of their top-8 run FROM SMEM-STAGED rows (chunks of 8
// entries through the dead A-tile region). Exact chain: sequential
// ascending-d __fmaf_rn over g_xn/g_en values (bit-exact vs rounds 4-6).
// ---------------------------------------------------------------------------
__global__ void __launch_bounds__(256, 2)
pq_mma_kernel(const float* __restrict__ embed,
              float* __restrict__ out,
              long long out_size) {
    extern __shared__ char smem[];
    const uint32_t sb = smem_u32(smem);
    int*   bc        = (int*)(smem + BC_OFF);
    int*   cnt       = (int*)(smem + CNT_OFF);      // [0]=nfix, [1]=ndeep
    int*   s_fixtok  = (int*)(smem + FIXTOK_OFF);
    int*   s_deeptok = (int*)(smem + DEEP_OFF);
    int*   s_top8c   = (int*)(smem + TOP8_OFF);
    float* s_rv      = (float*)(smem + RV_OFF);
    int*   s_ri      = (int*)(smem + RI_OFF);

    const int tid  = threadIdx.x;
    const int wid  = tid >> 5;
    const int lane = tid & 31;
    const int tok0 = blockIdx.x * TM;
    const int q = (tok0 % Nn) / MCHUNK;
    const __nv_bfloat16* Eb = g_enb + (size_t)q * Kc * Dd;

    if (tid == 0) { cnt[0] = 0; cnt[1] = 0; }

    // ---- stage A (128 tokens x 256 bf16, 528B rows) + B tile 0 ----
    for (int i = tid; i < TM * 32; i += 256) {
        int row = i >> 5, seg = i & 31;
        cp16(sb + A_OFF + (uint32_t)row * ROWB + (uint32_t)seg * 16,
             g_xnb + (size_t)(tok0 + row) * Dd + seg * 8);
    }
    for (int i = tid; i < TILE_N * 32; i += 256) {
        int row = i >> 5, seg = i & 31;
        cp16(sb + B0_OFF + (uint32_t)row * ROWB + (uint32_t)seg * 16,
             Eb + (size_t)row * Dd + seg * 8);
    }
    cp_commit();
    cp_wait<0>();
    __syncthreads();

    // A ldsm per-lane base (validated mapping from rounds 9/11)
    const uint32_t a_base = sb + A_OFF
        + (uint32_t)(wid * 16 + ((lane >> 3) & 1) * 8 + (lane & 7)) * ROWB
        + (uint32_t)((lane >> 4) * 8) * 2;

    // B ldsm per-lane offset: groups (bn,k0),(bn,k8),(bn+1,k0),(bn+1,k8)
    const uint32_t b_lane_off =
        (uint32_t)(((lane >> 4) & 1) * 8 + (lane & 7)) * ROWB +
        (uint32_t)(((lane >> 3) & 1) * 8) * 2;

    // per-thread top-8 for two token rows: A = lane>>2, B = lane>>2 + 8
    float tvA[8], tvB[8];
    int   tiA[8], tiB[8];
#pragma unroll
    for (int k = 0; k < 8; ++k) {
        tvA[k] = -3.4e38f; tiA[k] = 0x7fffffff;
        tvB[k] = -3.4e38f; tiB[k] = 0x7fffffff;
    }
    const int cb_lane = (lane & 3) * 2;

    for (int nt = 0; nt < NTILE; ++nt) {
        const uint32_t bbuf = sb + ((nt & 1) ? B1_OFF : B0_OFF);

        // prefetch B(nt+1) into the other buffer (overlaps compute)
        if (nt + 1 < NTILE) {
            uint32_t dstb = sb + (((nt + 1) & 1) ? B1_OFF : B0_OFF);
            for (int i = tid; i < TILE_N * 32; i += 256) {
                int row = i >> 5, seg = i & 31;
                cp16(dstb + (uint32_t)row * ROWB + (uint32_t)seg * 16,
                     Eb + (size_t)((nt + 1) * TILE_N + row) * Dd + seg * 8);
            }
            cp_commit();
        }

        // ---- compute: 16 tokens x 32 codes per warp, K=256 ----
        float c[4][4];
#pragma unroll
        for (int bn = 0; bn < 4; ++bn)
#pragma unroll
            for (int e = 0; e < 4; ++e) c[bn][e] = 0.f;

#pragma unroll
        for (int ks = 0; ks < KSTEPS; ++ks) {
            uint32_t a[4];
            ldsm_x4(a_base + ks * 32, a[0], a[1], a[2], a[3]);
            uint32_t bb[4][2];
#pragma unroll
            for (int p = 0; p < 2; ++p) {
                uint32_t addr = bbuf + (uint32_t)p * (16 * ROWB)
                                + (uint32_t)ks * 32 + b_lane_off;
                ldsm_x4(addr, bb[2 * p][0], bb[2 * p][1],
                        bb[2 * p + 1][0], bb[2 * p + 1][1]);
            }
#pragma unroll
            for (int bn = 0; bn < 4; ++bn)
                mma16816(c[bn], a, bb[bn][0], bb[bn][1]);
        }

        // ---- register fold into top-8 (rows lane>>2 and lane>>2+8) ----
#pragma unroll
        for (int bn = 0; bn < 4; ++bn) {
            const int cbase = nt * TILE_N + bn * 8 + cb_lane;
            if (c[bn][0] > tvA[7]) top8_insert(c[bn][0], cbase,     tvA, tiA);
            if (c[bn][1] > tvA[7]) top8_insert(c[bn][1], cbase + 1, tvA, tiA);
            if (c[bn][2] > tvB[7]) top8_insert(c[bn][2], cbase,     tvB, tiB);
            if (c[bn][3] > tvB[7]) top8_insert(c[bn][3], cbase + 1, tvB, tiB);
        }

        cp_wait<0>();
        __syncthreads();   // B(nt+1) landed; old buf free next iteration
    }

    // ---- merge top-8 across the 4 lanes sharing each token row ----
#pragma unroll
    for (int step = 1; step <= 2; step <<= 1) {
        float ov[8]; int oi[8];
#pragma unroll
        for (int k = 0; k < 8; ++k) {
            ov[k] = __shfl_xor_sync(0xffffffffu, tvA[k], step);
            oi[k] = __shfl_xor_sync(0xffffffffu, tiA[k], step);
        }
#pragma unroll
        for (int k = 0; k < 8; ++k)
            if (ov[k] > tvA[7] || (ov[k] == tvA[7] && oi[k] < tiA[7]))
                top8_insert(ov[k], oi[k], tvA, tiA);
#pragma unroll
        for (int k = 0; k < 8; ++k) {
            ov[k] = __shfl_xor_sync(0xffffffffu, tvB[k], step);
            oi[k] = __shfl_xor_sync(0xffffffffu, tiB[k], step);
        }
#pragma unroll
        for (int k = 0; k < 8; ++k)
            if (ov[k] > tvB[7] || (ov[k] == tvB[7] && oi[k] < tiB[7]))
                top8_insert(ov[k], oi[k], tvB, tiB);
    }

    // ---- in-block classification (lane&3 == 0 owns 2 tokens) ----
    if ((lane & 3) == 0) {
        const int r = lane >> 2;
#pragma unroll
        for (int h = 0; h < 2; ++h) {
            const float* tv = h ? tvB : tvA;
            const int*   ti = h ? tiB : tiA;
            int tlocal = wid * 16 + h * 8 + r;
            bc[tlocal] = ti[0];                      // provisional
            if (tv[0] - tv[1] < TAU) {
                if (tv[0] - tv[7] >= TAU) {
                    int p = atomicAdd(&cnt[0], 1);
                    s_fixtok[p] = tlocal;
#pragma unroll
                    for (int k = 0; k < 8; ++k) s_top8c[tlocal * 8 + k] = ti[k];
                } else {
                    int p = atomicAdd(&cnt[1], 1);
                    s_deeptok[p] = tlocal;
                }
            }
        }
    }
    __syncthreads();

    // ---- fix1-type: exact rescore of 8 candidates, SMEM-STAGED chunks ----
    // A region (dead) holds up to 64 e-rows at FROWB stride; B0 holds 8 x-rows.
    {
        const int nfix = cnt[0];
        float* es = (float*)(smem + A_OFF);
        float* xs = (float*)(smem + B0_OFF);
        for (int cb = 0; cb < nfix; cb += 8) {
            const int nent = min(8, nfix - cb);
            // stage e-rows: 64 float4 per row, rows = nent*8
            for (int i = tid; i < nent * 8 * 64; i += 256) {
                int row = i >> 6;          // 0..63
                int seg = i & 63;
                int code = s_top8c[s_fixtok[cb + (row >> 3)] * 8 + (row & 7)];
                cp16(sb + A_OFF + (uint32_t)row * FROWB + (uint32_t)seg * 16,
                     g_en + ((size_t)q * Kc + code) * Dd + seg * 4);
            }
            // stage x-rows: nent rows
            for (int i = tid; i < nent * 64; i += 256) {
                int row = i >> 6;
                int seg = i & 63;
                cp16(sb + B0_OFF + (uint32_t)row * FROWB + (uint32_t)seg * 16,
                     g_xn + (size_t)(tok0 + s_fixtok[cb + row]) * Dd + seg * 4);
            }
            cp_commit();
            cp_wait<0>();
            __syncthreads();

            // chains: threads 0..63, one per (entry, slot)
            float v = -3.4e38f;
            int   code = 0x7fffffff;
            if (tid < nent * 8) {
                const int e = tid >> 3;
                const int slot = tid & 7;
                code = s_top8c[s_fixtok[cb + e] * 8 + slot];
                const float* er = (const float*)((const char*)es + tid * FROWB);
                const float* xr = (const float*)((const char*)xs + e * FROWB);
                float acc = 0.f;
#pragma unroll 8
                for (int d = 0; d < Dd; ++d) acc = __fmaf_rn(xr[d], er[d], acc);
                v = acc;
            }
            // reduce within aligned groups of 8 lanes (threads 0..63 only)
            if (tid < 64) {
#pragma unroll
                for (int o = 4; o; o >>= 1) {
                    float ov = __shfl_down_sync(0xffffffffu, v, o);
                    int   oi = __shfl_down_sync(0xffffffffu, code, o);
                    if (ov > v || (ov == v && oi < code)) { v = ov; code = oi; }
                }
                if ((tid & 7) == 0 && (tid >> 3) < nent)
                    bc[s_fixtok[cb + (tid >> 3)]] = code;
            }
            __syncthreads();   // before next chunk overwrites staging
        }
    }
    __syncthreads();

    // ---- deep ties (rare): full exact 2048-scan, one token at a time ----
    {
        const int ndeep = cnt[1];
        for (int e = 0; e < ndeep; ++e) {
            const int tl = s_deeptok[e];
            const float* xr = g_xn + (size_t)(tok0 + tl) * Dd;
            float best = -3.4e38f;
            int   bi = 0x7fffffff;
            for (int c0 = tid; c0 < Kc; c0 += 256) {
                const float* er = g_en + ((size_t)q * Kc + c0) * Dd;
                float acc = 0.f;
#pragma unroll 8
                for (int d = 0; d < Dd; ++d) acc = __fmaf_rn(xr[d], er[d], acc);
                if (acc > best) { best = acc; bi = c0; }   // ascending: lowest kept
            }
            s_rv[tid] = best;
            s_ri[tid] = bi;
            __syncthreads();
            if (tid == 0) {
                float v = -3.4e38f;
                int   i = 0x7fffffff;
                for (int t = 0; t < 256; ++t)
                    if (s_rv[t] > v || (s_rv[t] == v && s_ri[t] < i)) {
                        v = s_rv[t]; i = s_ri[t];
                    }
                bc[tl] = i;
            }
            __syncthreads();
        }
    }

    // ---- final outputs: encoding + raw-codeword gather (coalesced) ----
    if (tid < TM) {
        long long epos = (long long)NTOK * Dd + (tok0 + tid);
        if (epos < out_size) out[epos] = (float)bc[tid];
    }
    __syncthreads();
    const float* Eqraw = embed + (size_t)q * Kc * Dd;
    for (int i = tid; i < TM * (Dd / 4); i += 256) {
        int token = i >> 6;
        int r = i & 63;
        int code = bc[token];
        ((float4*)(out + (size_t)(tok0 + token) * Dd))[r] =
            ((const float4*)(Eqraw + (size_t)code * Dd))[r];
    }
}

// ---------------------------------------------------------------------------
// Tail: zero-fill vq_loss (and any slack) past quantized+encoding.
// ---------------------------------------------------------------------------
__global__ void zero_tail(float* __restrict__ out, long long start, long long end) {
    long long i = start + (long long)blockIdx.x * blockDim.x + threadIdx.x;
    if (i < end) out[i] = 0.f;
}

extern "C" void kernel_launch(void* const* d_in, const int* in_sizes, int n_in,
                              void* d_out, int out_size) {
    const float* x     = (const float*)d_in[0];
    const float* embed = (const float*)d_in[1];
    if (n_in >= 2 && in_sizes[0] == Qn * Kc * Dd && in_sizes[1] == NTOK * Dd) {
        const float* t = x; x = embed; embed = t;
    }
    float* out = (float*)d_out;

    l2norm_e_kernel<<<(Qn * Kc) / 8, 256>>>(embed);
    l2norm_x_kernel<<<NTOK / 8, 256>>>(x);

    long long tail = (long long)NTOK * Dd + NTOK;
    if ((long long)out_size > tail) {
        long long n = (long long)out_size - tail;
        int blocks = (int)((n + 255) / 256);
        zero_tail<<<blocks, 256>>>(out, tail, (long long)out_size);
    }

    cudaFuncSetAttribute(pq_mma_kernel, cudaFuncAttributeMaxDynamicSharedMemorySize,
                         SMEM_TOTAL);
    pq_mma_kernel<<<NTOK / TM, 256, SMEM_TOTAL>>>(embed, out, (long long)out_size);
}